// round 7
// baseline (speedup 1.0000x reference)
#include <cuda_runtime.h>
#include <cstdint>
#include <cstddef>

// Problem constants
#define NODES   49152
#define FDIM    128
#define DTOT    9
#define NB      12      // nodes per CTA
#define THREADS 384     // 3 groups x 128 threads; each group handles 4 nodes
#define NGRP    4

typedef unsigned long long ull;

// packed f32x2 helpers (sm_103a)
#define FMA2(d_, a_, b_, c_) \
    asm("fma.rn.f32x2 %0, %1, %2, %3;" : "=l"(d_) : "l"(a_), "l"(b_), "l"(c_))
#define PACKDUP(d_, f_) \
    asm("mov.b64 %0, {%1, %1};" : "=l"(d_) : "r"(__float_as_uint(f_)))
#define UNPACK2(lo_, hi_, x_) \
    asm("mov.b64 {%0, %1}, %2;" : "=r"(lo_), "=r"(hi_) : "l"(x_))

// smem float map
//  T_s : [128 u][12 d][12 n] = 18432   (later overlaid by TU [12 n][1152])
//  WREG: 33024   (3 weight chunk tiles 128x65=8320 each | ls_w 256x129 | lvw 128x129)
//  SB  : [12][128] = 1536
//  PB  : [12][256] = 3072
//  SS2 : [128][12] = 1536
#define OFF_T    0
#define OFF_WREG 18432
#define OFF_SB   51456
#define OFF_PB   52992
#define OFF_SS2  56064
// total 57600 floats = 230400 bytes
#define WPITCH   65
#define WTILE    8320      // 128*65

// stage one 128x64 u-chunk of a weight matrix, untransposed [v][65], conflict-free
static __device__ __forceinline__ void stage_wchunk(float* __restrict__ dst,
                                                    const float* __restrict__ src,
                                                    int chunk, int tid) {
    const float* s = src + chunk * 64;
    for (int i = tid; i < 8192; i += THREADS) {       // 128 v x 64 u
        int vrow = i >> 6;
        int ul   = i & 63;
        dst[vrow * WPITCH + ul] = s[vrow * 128 + ul]; // LDG coalesced; STS banks (v+u)%32
    }
}

// fused q/k/v accumulation for one irrep block over one 64-u chunk
template<int OFF, int DD>
static __device__ __forceinline__ void fused_chunk(const float* __restrict__ T_s,
                                                   const float* __restrict__ WQc,
                                                   const float* __restrict__ WKc,
                                                   const float* __restrict__ WVc,
                                                   int v, int ng, int chunk,
                                                   ull aq[2][DD], ull ak[2][DD], ull av[2][DD]) {
    const int ubase = chunk * 64;
    #pragma unroll 2
    for (int ul = 0; ul < 64; ul++) {
        float wq = WQc[v * WPITCH + ul];
        float wk = WKc[v * WPITCH + ul];
        float wv = WVc[v * WPITCH + ul];
        ull wq2, wk2, wv2;
        PACKDUP(wq2, wq);
        PACKDUP(wk2, wk);
        PACKDUP(wv2, wv);
        const float* tb = T_s + ((ubase + ul) * 12 + OFF) * 12 + ng;
        #pragma unroll
        for (int d = 0; d < DD; d++) {
            ulonglong2 t = *reinterpret_cast<const ulonglong2*>(tb + d * 12);
            FMA2(aq[0][d], wq2, t.x, aq[0][d]);
            FMA2(aq[1][d], wq2, t.y, aq[1][d]);
            FMA2(ak[0][d], wk2, t.x, ak[0][d]);
            FMA2(ak[1][d], wk2, t.y, ak[1][d]);
            FMA2(av[0][d], wv2, t.x, av[0][d]);
            FMA2(av[1][d], wv2, t.y, av[1][d]);
        }
    }
}

template<int DD>
static __device__ __forceinline__ void finalize_qk(ull aq[2][DD], ull ak[2][DD],
                                                   float cf, float s_reg[NGRP]) {
    #pragma unroll
    for (int p = 0; p < 2; p++) {
        ull acc = 0ull;
        #pragma unroll
        for (int d = 0; d < DD; d++) FMA2(acc, aq[p][d], ak[p][d], acc);
        unsigned lo, hi;
        UNPACK2(lo, hi, acc);
        s_reg[2 * p + 0] += cf * __uint_as_float(lo);
        s_reg[2 * p + 1] += cf * __uint_as_float(hi);
    }
}

__global__ void __launch_bounds__(THREADS, 1)
tp_attn_kernel(const float* __restrict__ Tg, const float* __restrict__ Sg,
               const float* __restrict__ Wq, const float* __restrict__ Wk,
               const float* __restrict__ Wv, const float* __restrict__ w2,
               const float* __restrict__ lsw, const float* __restrict__ lsb,
               const float* __restrict__ lvw, const float* __restrict__ lvb,
               float* __restrict__ outT, float* __restrict__ out2) {
    extern __shared__ float smem[];
    float* T_s  = smem + OFF_T;
    float* WREG = smem + OFF_WREG;
    float* SB   = smem + OFF_SB;
    float* PB   = smem + OFF_PB;
    float* SS2  = smem + OFF_SS2;
    float* TU_s = T_s;                       // overlay after fused passes

    float* WQc = WREG;
    float* WKc = WREG + WTILE;
    float* WVc = WREG + 2 * WTILE;

    const int tid   = threadIdx.x;
    const int lane  = tid & 31;
    const int wid   = tid >> 5;
    const int v     = tid & 127;
    const int ng    = (tid >> 7) * NGRP;     // node base for this group (0,4,8)
    const int node0 = blockIdx.x * NB;

    // ---- stage T tile: global [n][u][9] -> smem [u][d][n]
    {
        const float4* g4 = reinterpret_cast<const float4*>(Tg + (size_t)node0 * (FDIM * DTOT));
        #pragma unroll
        for (int it = 0; it < 9; it++) {
            int i = it * THREADS + tid;
            float4 t = g4[i];
            float a[4] = { t.x, t.y, t.z, t.w };
            int e = i << 2;
            #pragma unroll
            for (int z = 0; z < 4; z++) {
                int ee = e + z;
                int n = ee / 1152;
                int r = ee - n * 1152;
                int u = r / 9;
                int d = r - u * 9;
                T_s[(u * 12 + d) * 12 + n] = a[z];
            }
        }
    }

    float s_reg[NGRP] = { 0.f, 0.f, 0.f, 0.f };
    ull av2[2][5], av1[2][3], av0[2][1];
    #pragma unroll
    for (int p = 0; p < 2; p++) {
        #pragma unroll
        for (int d = 0; d < 5; d++) av2[p][d] = 0ull;
        #pragma unroll
        for (int d = 0; d < 3; d++) av1[p][d] = 0ull;
        av0[p][0] = 0ull;
    }

    // ---- fused q/k/v passes, irrep l=2 first (peak regs when nothing carried)
    {
        ull aq[2][5], ak[2][5];
        #pragma unroll
        for (int p = 0; p < 2; p++)
            #pragma unroll
            for (int d = 0; d < 5; d++) { aq[p][d] = 0ull; ak[p][d] = 0ull; }
        #pragma unroll 1
        for (int c = 0; c < 2; c++) {
            __syncthreads();
            stage_wchunk(WQc, Wq + 32768, c, tid);
            stage_wchunk(WKc, Wk + 32768, c, tid);
            stage_wchunk(WVc, Wv + 32768, c, tid);
            __syncthreads();
            fused_chunk<4, 5>(T_s, WQc, WKc, WVc, v, ng, c, aq, ak, av2);
        }
        finalize_qk<5>(aq, ak, 0.0020171788261496963f, s_reg);  // (1/sqrt15)/128
    }
    {
        ull aq[2][3], ak[2][3];
        #pragma unroll
        for (int p = 0; p < 2; p++)
            #pragma unroll
            for (int d = 0; d < 3; d++) { aq[p][d] = 0ull; ak[p][d] = 0ull; }
        #pragma unroll 1
        for (int c = 0; c < 2; c++) {
            __syncthreads();
            stage_wchunk(WQc, Wq + 16384, c, tid);
            stage_wchunk(WKc, Wk + 16384, c, tid);
            stage_wchunk(WVc, Wv + 16384, c, tid);
            __syncthreads();
            fused_chunk<1, 3>(T_s, WQc, WKc, WVc, v, ng, c, aq, ak, av1);
        }
        finalize_qk<3>(aq, ak, 0.0026041666666666665f, s_reg);  // (1/3)/128
    }
    {
        ull aq[2][1], ak[2][1];
        #pragma unroll
        for (int p = 0; p < 2; p++) { aq[p][0] = 0ull; ak[p][0] = 0ull; }
        #pragma unroll 1
        for (int c = 0; c < 2; c++) {
            __syncthreads();
            stage_wchunk(WQc, Wq, c, tid);
            stage_wchunk(WKc, Wk, c, tid);
            stage_wchunk(WVc, Wv, c, tid);
            __syncthreads();
            fused_chunk<0, 1>(T_s, WQc, WKc, WVc, v, ng, c, aq, ak, av0);
        }
        finalize_qk<1>(aq, ak, 0.0045105489780439515f, s_reg);  // (1/sqrt3)/128
    }

    #pragma unroll
    for (int j = 0; j < NGRP; j++) SB[(ng + j) * 128 + v] = s_reg[j];
    __syncthreads();

    // ---- stage ls_w untransposed [j][129] (conflict-free scalar copy)
    for (int i = tid; i < 32768; i += THREADS) {
        int jrow = i >> 7;
        int u    = i & 127;
        WREG[jrow * 129 + u] = lsw[i];
    }
    __syncthreads();

    // ---- pass B: logits + softmax. One warp per node.
    {
        int n = wid;
        float acc[8] = { 0.f, 0.f, 0.f, 0.f, 0.f, 0.f, 0.f, 0.f };
        const float* srow = SB + n * 128;
        #pragma unroll 2
        for (int u = 0; u < 128; u++) {
            float sv = srow[u];
            #pragma unroll
            for (int kk = 0; kk < 8; kk++)
                acc[kk] = fmaf(sv, WREG[(lane + (kk << 5)) * 129 + u], acc[kk]);
        }
        #pragma unroll
        for (int kk = 0; kk < 8; kk++) acc[kk] += lsb[(kk << 5) + lane];
        float m = acc[0];
        #pragma unroll
        for (int kk = 1; kk < 8; kk++) m = fmaxf(m, acc[kk]);
        #pragma unroll
        for (int off = 16; off > 0; off >>= 1)
            m = fmaxf(m, __shfl_xor_sync(0xffffffffu, m, off));
        float ssum = 0.f;
        #pragma unroll
        for (int kk = 0; kk < 8; kk++) { acc[kk] = __expf(acc[kk] - m); ssum += acc[kk]; }
        #pragma unroll
        for (int off = 16; off > 0; off >>= 1)
            ssum += __shfl_xor_sync(0xffffffffu, ssum, off);
        float inv = 1.f / ssum;
        #pragma unroll
        for (int kk = 0; kk < 8; kk++)
            PB[n * 256 + (kk << 5) + lane] = acc[kk] * inv;
    }
    __syncthreads();   // PB ready; T_s reads all done -> TU overlay OK; WREG reusable

    // ---- TU: apply full scale (sd * w2 / sqrtF) from registers, store to smem
    {
        const float INV_SQRT_F = 0.08838834764831845f;
        float w20 = w2[v]       * INV_SQRT_F;
        float w21 = w2[128 + v] * INV_SQRT_F;
        float w22 = w2[256 + v] * INV_SQRT_F;
        #pragma unroll
        for (int p = 0; p < 2; p++) {
            int n0 = ng + 2 * p;
            float sd0 = PB[(n0 + 0) * 256 + 128 + v];
            float sd1 = PB[(n0 + 1) * 256 + 128 + v];
            float* t0 = TU_s + (n0 + 0) * 1152 + v * 9;
            float* t1 = TU_s + (n0 + 1) * 1152 + v * 9;
            unsigned lo, hi;
            // l0 (d=0)
            UNPACK2(lo, hi, av0[p][0]);
            t0[0] = sd0 * w20 * __uint_as_float(lo);
            t1[0] = sd1 * w20 * __uint_as_float(hi);
            // l1 (d=1..3)
            #pragma unroll
            for (int d = 0; d < 3; d++) {
                UNPACK2(lo, hi, av1[p][d]);
                t0[1 + d] = sd0 * w21 * __uint_as_float(lo);
                t1[1 + d] = sd1 * w21 * __uint_as_float(hi);
            }
            // l2 (d=4..8)
            #pragma unroll
            for (int d = 0; d < 5; d++) {
                UNPACK2(lo, hi, av2[p][d]);
                t0[4 + d] = sd0 * w22 * __uint_as_float(lo);
                t1[4 + d] = sd1 * w22 * __uint_as_float(hi);
            }
        }
    }

    // ---- stage lvw [v][129] + S transposed SS2[c][n]
    for (int i = tid; i < 16384; i += THREADS) {
        int vrow = i >> 7;
        int u    = i & 127;
        WREG[vrow * 129 + u] = lvw[i];
    }
    {
        int i = tid;                                // 1536/4 float4, one per thread
        float4 t = reinterpret_cast<const float4*>(Sg + (size_t)node0 * FDIM)[i];
        float a[4] = { t.x, t.y, t.z, t.w };
        int e = i << 2;
        #pragma unroll
        for (int z = 0; z < 4; z++) {
            int ee = e + z;
            int n = ee >> 7;
            int c = ee & 127;
            SS2[c * 12 + n] = a[z];
        }
    }
    __syncthreads();

    // ---- out2: su * silu(S @ lvs_w^T + b)
    {
        ull acc2[2] = { 0ull, 0ull };
        #pragma unroll 2
        for (int c = 0; c < 128; c++) {
            float w = WREG[v * 129 + c];
            ull w2p;
            PACKDUP(w2p, w);
            ulonglong2 t = *reinterpret_cast<const ulonglong2*>(SS2 + c * 12 + ng);
            FMA2(acc2[0], w2p, t.x, acc2[0]);
            FMA2(acc2[1], w2p, t.y, acc2[1]);
        }
        float b = lvb[v];
        float zz[4];
        {
            unsigned lo, hi;
            UNPACK2(lo, hi, acc2[0]);
            zz[0] = __uint_as_float(lo); zz[1] = __uint_as_float(hi);
            UNPACK2(lo, hi, acc2[1]);
            zz[2] = __uint_as_float(lo); zz[3] = __uint_as_float(hi);
        }
        #pragma unroll
        for (int j = 0; j < NGRP; j++) {
            int n = ng + j;
            float z   = zz[j] + b;
            float sig = 1.f / (1.f + __expf(-z));
            out2[(size_t)(node0 + n) * FDIM + v] = PB[n * 256 + v] * (z * sig);
        }
    }

    // ---- flush TU: pure coalesced float4 copy
    {
        float4* gout = reinterpret_cast<float4*>(outT + (size_t)node0 * (FDIM * DTOT));
        const float4* s4 = reinterpret_cast<const float4*>(TU_s);
        #pragma unroll
        for (int it = 0; it < 9; it++)
            gout[it * THREADS + tid] = s4[it * THREADS + tid];
    }
}

extern "C" void kernel_launch(void* const* d_in, const int* in_sizes, int n_in,
                              void* d_out, int out_size) {
    const float* Tg  = (const float*)d_in[0];
    const float* Sg  = (const float*)d_in[1];
    const float* Wq  = (const float*)d_in[2];
    const float* Wk  = (const float*)d_in[3];
    const float* Wv  = (const float*)d_in[4];
    const float* w2  = (const float*)d_in[5];
    const float* lsw = (const float*)d_in[6];
    const float* lsb = (const float*)d_in[7];
    const float* lvw = (const float*)d_in[8];
    const float* lvb = (const float*)d_in[9];

    float* out  = (float*)d_out;
    float* outT = out;
    float* out2 = out + (size_t)NODES * FDIM * DTOT;

    const int smem_bytes = 230400;
    cudaFuncSetAttribute(tp_attn_kernel,
                         cudaFuncAttributeMaxDynamicSharedMemorySize, smem_bytes);
    tp_attn_kernel<<<NODES / NB, THREADS, smem_bytes>>>(
        Tg, Sg, Wq, Wk, Wv, w2, lsw, lsb, lvw, lvb, outT, out2);
}

// round 8
// speedup vs baseline: 1.1079x; 1.1079x over previous
#include <cuda_runtime.h>
#include <cstdint>
#include <cstddef>

// Problem constants
#define NODES   49152
#define FDIM    128
#define DTOT    9
#define NB      12      // nodes per CTA
#define THREADS 768     // 6 groups x 128 threads; each group handles 2 nodes (1 packed pair)

typedef unsigned long long ull;

// packed f32x2 helpers (sm_103a)
#define FMA2(d_, a_, b_, c_) \
    asm("fma.rn.f32x2 %0, %1, %2, %3;" : "=l"(d_) : "l"(a_), "l"(b_), "l"(c_))
#define PACKDUP(d_, f_) \
    asm("mov.b64 %0, {%1, %1};" : "=l"(d_) : "r"(__float_as_uint(f_)))
#define UNPACK2(lo_, hi_, x_) \
    asm("mov.b64 {%0, %1}, %2;" : "=r"(lo_), "=r"(hi_) : "l"(x_))

// smem float map (total 52992 floats = 211968 bytes)
//  T_s : [128 u][9 d][12 n] = 13824   (later overlaid by TU [12 n][1152])
//  SBt : [128 v][12 n]      =  1536
//  PB  : [12 n][256]        =  3072
//  SS2 : [128 c][12 n]      =  1536
//  WREG: 33024  (3 weight chunks 128x65 | ls_w 256x129 | lvw 128x129)
#define OFF_T    0
#define OFF_SBT  13824
#define OFF_PB   15360
#define OFF_SS2  18432
#define OFF_WREG 19968
#define SMEM_FLOATS 52992
#define WPITCH   65
#define WTILE    8320      // 128*65

// stage one 128x64 u-chunk of a weight matrix, untransposed [v][65], conflict-free
static __device__ __forceinline__ void stage_wchunk(float* __restrict__ dst,
                                                    const float* __restrict__ src,
                                                    int chunk, int tid) {
    const float* s = src + chunk * 64;
    for (int i = tid; i < 8192; i += THREADS) {       // 128 v x 64 u
        int vrow = i >> 6;
        int ul   = i & 63;
        dst[vrow * WPITCH + ul] = s[vrow * 128 + ul]; // LDG coalesced; STS banks (v+u)%32
    }
}

// fused q/k/v accumulation for one irrep block over one 64-u chunk (1 node pair)
template<int OFF, int DD>
static __device__ __forceinline__ void fused_chunk(const float* __restrict__ T_s,
                                                   const float* __restrict__ WQc,
                                                   const float* __restrict__ WKc,
                                                   const float* __restrict__ WVc,
                                                   int v, int ng, int chunk,
                                                   ull aq[DD], ull ak[DD], ull av[DD]) {
    const int ubase = chunk * 64;
    #pragma unroll 2
    for (int ul = 0; ul < 64; ul++) {
        float wq = WQc[v * WPITCH + ul];
        float wk = WKc[v * WPITCH + ul];
        float wv = WVc[v * WPITCH + ul];
        ull wq2, wk2, wv2;
        PACKDUP(wq2, wq);
        PACKDUP(wk2, wk);
        PACKDUP(wv2, wv);
        const float* tb = T_s + ((ubase + ul) * 9 + OFF) * 12 + ng;
        #pragma unroll
        for (int d = 0; d < DD; d++) {
            ull t = *reinterpret_cast<const ull*>(tb + d * 12);   // LDS.64, 8B-aligned
            FMA2(aq[d], wq2, t, aq[d]);
            FMA2(ak[d], wk2, t, ak[d]);
            FMA2(av[d], wv2, t, av[d]);
        }
    }
}

template<int DD>
static __device__ __forceinline__ void finalize_qk(ull aq[DD], ull ak[DD],
                                                   float cf, float s_reg[2]) {
    ull acc = 0ull;
    #pragma unroll
    for (int d = 0; d < DD; d++) FMA2(acc, aq[d], ak[d], acc);
    unsigned lo, hi;
    UNPACK2(lo, hi, acc);
    s_reg[0] += cf * __uint_as_float(lo);
    s_reg[1] += cf * __uint_as_float(hi);
}

__global__ void __launch_bounds__(THREADS, 1)
tp_attn_kernel(const float* __restrict__ Tg, const float* __restrict__ Sg,
               const float* __restrict__ Wq, const float* __restrict__ Wk,
               const float* __restrict__ Wv, const float* __restrict__ w2,
               const float* __restrict__ lsw, const float* __restrict__ lsb,
               const float* __restrict__ lvw, const float* __restrict__ lvb,
               float* __restrict__ outT, float* __restrict__ out2) {
    extern __shared__ float smem[];
    float* T_s  = smem + OFF_T;
    float* SBt  = smem + OFF_SBT;
    float* PB   = smem + OFF_PB;
    float* SS2  = smem + OFF_SS2;
    float* WREG = smem + OFF_WREG;
    float* TU_s = T_s;                       // overlay after fused passes

    float* WQc = WREG;
    float* WKc = WREG + WTILE;
    float* WVc = WREG + 2 * WTILE;

    const int tid   = threadIdx.x;
    const int lane  = tid & 31;
    const int wid   = tid >> 5;
    const int v     = tid & 127;
    const int ng    = (tid >> 7) * 2;        // node pair base: 0,2,4,6,8,10
    const int node0 = blockIdx.x * NB;

    // ---- stage T tile: global [n][u][9] -> smem [u][d][n]; stage S -> SS2[c][n]
    {
        const float4* g4 = reinterpret_cast<const float4*>(Tg + (size_t)node0 * (FDIM * DTOT));
        for (int i = tid; i < 3456; i += THREADS) {
            float4 t = g4[i];
            float a[4] = { t.x, t.y, t.z, t.w };
            int e = i << 2;
            #pragma unroll
            for (int z = 0; z < 4; z++) {
                int ee = e + z;
                int n = ee / 1152;
                int r = ee - n * 1152;
                int u = r / 9;
                int d = r - u * 9;
                T_s[(u * 9 + d) * 12 + n] = a[z];
            }
        }
        if (tid < 384) {
            float4 t = reinterpret_cast<const float4*>(Sg + (size_t)node0 * FDIM)[tid];
            float a[4] = { t.x, t.y, t.z, t.w };
            int e = tid << 2;
            #pragma unroll
            for (int z = 0; z < 4; z++) {
                int ee = e + z;
                int n = ee >> 7;
                int c = ee & 127;
                SS2[c * 12 + n] = a[z];
            }
        }
    }

    float s_reg[2] = { 0.f, 0.f };
    ull av2[5], av1[3], av0[1];

    // ---- fused q/k/v passes, irrep l=2 first (peak regs when nothing carried)
    {
        ull aq[5], ak[5];
        #pragma unroll
        for (int d = 0; d < 5; d++) { aq[d] = 0ull; ak[d] = 0ull; av2[d] = 0ull; }
        #pragma unroll 1
        for (int c = 0; c < 2; c++) {
            __syncthreads();
            stage_wchunk(WQc, Wq + 32768, c, tid);
            stage_wchunk(WKc, Wk + 32768, c, tid);
            stage_wchunk(WVc, Wv + 32768, c, tid);
            __syncthreads();
            fused_chunk<4, 5>(T_s, WQc, WKc, WVc, v, ng, c, aq, ak, av2);
        }
        finalize_qk<5>(aq, ak, 0.0020171788261496963f, s_reg);  // (1/sqrt15)/128
    }
    {
        ull aq[3], ak[3];
        #pragma unroll
        for (int d = 0; d < 3; d++) { aq[d] = 0ull; ak[d] = 0ull; av1[d] = 0ull; }
        #pragma unroll 1
        for (int c = 0; c < 2; c++) {
            __syncthreads();
            stage_wchunk(WQc, Wq + 16384, c, tid);
            stage_wchunk(WKc, Wk + 16384, c, tid);
            stage_wchunk(WVc, Wv + 16384, c, tid);
            __syncthreads();
            fused_chunk<1, 3>(T_s, WQc, WKc, WVc, v, ng, c, aq, ak, av1);
        }
        finalize_qk<3>(aq, ak, 0.0026041666666666665f, s_reg);  // (1/3)/128
    }
    {
        ull aq[1], ak[1];
        aq[0] = 0ull; ak[0] = 0ull; av0[0] = 0ull;
        #pragma unroll 1
        for (int c = 0; c < 2; c++) {
            __syncthreads();
            stage_wchunk(WQc, Wq, c, tid);
            stage_wchunk(WKc, Wk, c, tid);
            stage_wchunk(WVc, Wv, c, tid);
            __syncthreads();
            fused_chunk<0, 1>(T_s, WQc, WKc, WVc, v, ng, c, aq, ak, av0);
        }
        finalize_qk<1>(aq, ak, 0.0045105489780439515f, s_reg);  // (1/sqrt3)/128
    }

    // s -> SBt[v][n]
    SBt[v * 12 + ng + 0] = s_reg[0];
    SBt[v * 12 + ng + 1] = s_reg[1];
    __syncthreads();   // all fused reads of WREG done; SBt ready

    // ---- stage ls_w untransposed [j][129] (conflict-free scalar copy)
    for (int i = tid; i < 32768; i += THREADS) {
        int jrow = i >> 7;
        int u    = i & 127;
        WREG[jrow * 129 + u] = lsw[i];
    }
    __syncthreads();

    // ---- logits: 2 warps per node; each lane owns 4 of 128 j in its half
    {
        int n    = wid >> 1;
        int half = wid & 1;
        float acc[4] = { 0.f, 0.f, 0.f, 0.f };
        #pragma unroll 2
        for (int u = 0; u < 128; u++) {
            float sv = SBt[u * 12 + n];
            #pragma unroll
            for (int kk = 0; kk < 4; kk++) {
                int j = half * 128 + (kk << 5) + lane;
                acc[kk] = fmaf(sv, WREG[j * 129 + u], acc[kk]);
            }
        }
        #pragma unroll
        for (int kk = 0; kk < 4; kk++) {
            int j = half * 128 + (kk << 5) + lane;
            PB[n * 256 + j] = acc[kk] + lsb[j];
        }
    }
    __syncthreads();

    // ---- softmax: warp per node (first 12 warps)
    if (wid < 12) {
        int n = wid;
        float acc[8];
        #pragma unroll
        for (int kk = 0; kk < 8; kk++) acc[kk] = PB[n * 256 + (kk << 5) + lane];
        float m = acc[0];
        #pragma unroll
        for (int kk = 1; kk < 8; kk++) m = fmaxf(m, acc[kk]);
        #pragma unroll
        for (int off = 16; off > 0; off >>= 1)
            m = fmaxf(m, __shfl_xor_sync(0xffffffffu, m, off));
        float ssum = 0.f;
        #pragma unroll
        for (int kk = 0; kk < 8; kk++) { acc[kk] = __expf(acc[kk] - m); ssum += acc[kk]; }
        #pragma unroll
        for (int off = 16; off > 0; off >>= 1)
            ssum += __shfl_xor_sync(0xffffffffu, ssum, off);
        float inv = 1.f / ssum;
        #pragma unroll
        for (int kk = 0; kk < 8; kk++)
            PB[n * 256 + (kk << 5) + lane] = acc[kk] * inv;
    }
    __syncthreads();

    // ---- TU: apply full scale (sd * w2 / sqrtF) from registers, store to smem overlay
    {
        const float INV_SQRT_F = 0.08838834764831845f;
        float w20 = w2[v]       * INV_SQRT_F;
        float w21 = w2[128 + v] * INV_SQRT_F;
        float w22 = w2[256 + v] * INV_SQRT_F;
        float sd0 = PB[(ng + 0) * 256 + 128 + v];
        float sd1 = PB[(ng + 1) * 256 + 128 + v];
        float* t0 = TU_s + (ng + 0) * 1152 + v * 9;
        float* t1 = TU_s + (ng + 1) * 1152 + v * 9;
        unsigned lo, hi;
        UNPACK2(lo, hi, av0[0]);
        t0[0] = sd0 * w20 * __uint_as_float(lo);
        t1[0] = sd1 * w20 * __uint_as_float(hi);
        #pragma unroll
        for (int d = 0; d < 3; d++) {
            UNPACK2(lo, hi, av1[d]);
            t0[1 + d] = sd0 * w21 * __uint_as_float(lo);
            t1[1 + d] = sd1 * w21 * __uint_as_float(hi);
        }
        #pragma unroll
        for (int d = 0; d < 5; d++) {
            UNPACK2(lo, hi, av2[d]);
            t0[4 + d] = sd0 * w22 * __uint_as_float(lo);
            t1[4 + d] = sd1 * w22 * __uint_as_float(hi);
        }
    }

    // ---- stage lvw [v][129] (overwrites ls_w region; logits reads done)
    for (int i = tid; i < 16384; i += THREADS) {
        int vrow = i >> 7;
        int u    = i & 127;
        WREG[vrow * 129 + u] = lvw[i];
    }
    __syncthreads();

    // ---- out2: su * silu(S @ lvs_w^T + b)
    {
        ull acc2 = 0ull;
        #pragma unroll 2
        for (int c = 0; c < 128; c++) {
            float w = WREG[v * 129 + c];
            ull w2p;
            PACKDUP(w2p, w);
            ull t = *reinterpret_cast<const ull*>(SS2 + c * 12 + ng);
            FMA2(acc2, w2p, t, acc2);
        }
        float b = lvb[v];
        unsigned lo, hi;
        UNPACK2(lo, hi, acc2);
        float zz[2] = { __uint_as_float(lo), __uint_as_float(hi) };
        #pragma unroll
        for (int j = 0; j < 2; j++) {
            int n = ng + j;
            float z   = zz[j] + b;
            float sig = 1.f / (1.f + __expf(-z));
            out2[(size_t)(node0 + n) * FDIM + v] = PB[n * 256 + v] * (z * sig);
        }
    }

    // ---- flush TU: pure coalesced float4 copy (TU writes synced above)
    {
        float4* gout = reinterpret_cast<float4*>(outT + (size_t)node0 * (FDIM * DTOT));
        const float4* s4 = reinterpret_cast<const float4*>(TU_s);
        for (int i = tid; i < 3456; i += THREADS)
            gout[i] = s4[i];
    }
}

extern "C" void kernel_launch(void* const* d_in, const int* in_sizes, int n_in,
                              void* d_out, int out_size) {
    const float* Tg  = (const float*)d_in[0];
    const float* Sg  = (const float*)d_in[1];
    const float* Wq  = (const float*)d_in[2];
    const float* Wk  = (const float*)d_in[3];
    const float* Wv  = (const float*)d_in[4];
    const float* w2  = (const float*)d_in[5];
    const float* lsw = (const float*)d_in[6];
    const float* lsb = (const float*)d_in[7];
    const float* lvw = (const float*)d_in[8];
    const float* lvb = (const float*)d_in[9];

    float* out  = (float*)d_out;
    float* outT = out;
    float* out2 = out + (size_t)NODES * FDIM * DTOT;

    const int smem_bytes = SMEM_FLOATS * 4;   // 211968
    cudaFuncSetAttribute(tp_attn_kernel,
                         cudaFuncAttributeMaxDynamicSharedMemorySize, smem_bytes);
    tp_attn_kernel<<<NODES / NB, THREADS, smem_bytes>>>(
        Tg, Sg, Wq, Wk, Wv, w2, lsw, lsb, lvw, lvb, outT, out2);
}